// round 1
// baseline (speedup 1.0000x reference)
#include <cuda_runtime.h>
#include <math.h>

#define En 4000
#define Sn 25
#define Qn 75
#define FEATn 64
#define HIDn 128
#define WAYn 5
#define ITERSn 10
#define LRc 0.01f

#define JSTR 132      // padded row stride for [*][HID] arrays (conflict-free)
#define NT 256

// ---- shared memory layout (float offsets) ----
#define OFF_W1T 0                            // W1 transposed: [FEAT][JSTR]
#define OFF_XS  (OFF_W1T + FEATn*JSTR)       // x (support / query chunk): [S][FEAT]
#define OFF_HS  (OFF_XS + Sn*FEATn)          // hidden acts: [S][JSTR]
#define OFF_DHS (OFF_HS + Sn*JSTR)           // hidden grads: [S][JSTR]
#define OFF_W2  (OFF_DHS + Sn*JSTR)          // W2: [WAY][JSTR]
#define OFF_LS  (OFF_W2 + WAYn*JSTR)         // logits: [S][8]
#define OFF_DLS (OFF_LS + Sn*8)              // dlogits: [S][8]
#define OFF_B1  (OFF_DLS + Sn*8)             // b1: [HID]
#define OFF_B2  (OFF_B1 + HIDn)              // b2: [8]
#define OFF_TG  (OFF_B2 + 8)                 // targets: 32 ints
#define SMEMF   (OFF_TG + 32)                // total floats = 17876 -> 71504 B

// fwd layer1: hs[s][j] = relu(sum_k xs[s][k] * W1T[k][j] + b1[j])
// thread layout: tj = tid&31 owns j in [4tj,4tj+4); r = tid>>5 owns s in {r, r+8, r+16, (r+24)}
__device__ __forceinline__ void fwd1(const float* __restrict__ xs,
                                     const float* __restrict__ W1T,
                                     const float* __restrict__ b1s,
                                     float* __restrict__ hs,
                                     int tj, int r)
{
    float4 bv = *(const float4*)&b1s[4*tj];
    float4 a0 = bv, a1 = bv, a2 = bv, a3 = bv;
    const bool has4 = (r == 0);              // warp-uniform (r+24 < 25 only for r==0)
    const float* x0 = xs + (r      ) * FEATn;
    const float* x1 = xs + (r +  8 ) * FEATn;
    const float* x2 = xs + (r + 16 ) * FEATn;
    const float* x3 = xs + (r + 24 ) * FEATn;

    if (has4) {
        #pragma unroll 4
        for (int k = 0; k < FEATn; ++k) {
            float4 wv = *(const float4*)&W1T[k*JSTR + 4*tj];
            float v0 = x0[k], v1 = x1[k], v2 = x2[k], v3 = x3[k];
            a0.x = fmaf(v0, wv.x, a0.x); a0.y = fmaf(v0, wv.y, a0.y);
            a0.z = fmaf(v0, wv.z, a0.z); a0.w = fmaf(v0, wv.w, a0.w);
            a1.x = fmaf(v1, wv.x, a1.x); a1.y = fmaf(v1, wv.y, a1.y);
            a1.z = fmaf(v1, wv.z, a1.z); a1.w = fmaf(v1, wv.w, a1.w);
            a2.x = fmaf(v2, wv.x, a2.x); a2.y = fmaf(v2, wv.y, a2.y);
            a2.z = fmaf(v2, wv.z, a2.z); a2.w = fmaf(v2, wv.w, a2.w);
            a3.x = fmaf(v3, wv.x, a3.x); a3.y = fmaf(v3, wv.y, a3.y);
            a3.z = fmaf(v3, wv.z, a3.z); a3.w = fmaf(v3, wv.w, a3.w);
        }
    } else {
        #pragma unroll 4
        for (int k = 0; k < FEATn; ++k) {
            float4 wv = *(const float4*)&W1T[k*JSTR + 4*tj];
            float v0 = x0[k], v1 = x1[k], v2 = x2[k];
            a0.x = fmaf(v0, wv.x, a0.x); a0.y = fmaf(v0, wv.y, a0.y);
            a0.z = fmaf(v0, wv.z, a0.z); a0.w = fmaf(v0, wv.w, a0.w);
            a1.x = fmaf(v1, wv.x, a1.x); a1.y = fmaf(v1, wv.y, a1.y);
            a1.z = fmaf(v1, wv.z, a1.z); a1.w = fmaf(v1, wv.w, a1.w);
            a2.x = fmaf(v2, wv.x, a2.x); a2.y = fmaf(v2, wv.y, a2.y);
            a2.z = fmaf(v2, wv.z, a2.z); a2.w = fmaf(v2, wv.w, a2.w);
        }
    }

    a0.x = fmaxf(a0.x, 0.f); a0.y = fmaxf(a0.y, 0.f); a0.z = fmaxf(a0.z, 0.f); a0.w = fmaxf(a0.w, 0.f);
    a1.x = fmaxf(a1.x, 0.f); a1.y = fmaxf(a1.y, 0.f); a1.z = fmaxf(a1.z, 0.f); a1.w = fmaxf(a1.w, 0.f);
    a2.x = fmaxf(a2.x, 0.f); a2.y = fmaxf(a2.y, 0.f); a2.z = fmaxf(a2.z, 0.f); a2.w = fmaxf(a2.w, 0.f);
    *(float4*)&hs[(r     ) * JSTR + 4*tj] = a0;
    *(float4*)&hs[(r +  8) * JSTR + 4*tj] = a1;
    *(float4*)&hs[(r + 16) * JSTR + 4*tj] = a2;
    if (has4) {
        a3.x = fmaxf(a3.x, 0.f); a3.y = fmaxf(a3.y, 0.f); a3.z = fmaxf(a3.z, 0.f); a3.w = fmaxf(a3.w, 0.f);
        *(float4*)&hs[(r + 24) * JSTR + 4*tj] = a3;
    }
}

// layer2 logit for one (s, c): sum_j hs[s][j] * W2[c][j] + b2[c]
__device__ __forceinline__ float fwd2_one(const float* __restrict__ hs,
                                          const float* __restrict__ W2s,
                                          const float* __restrict__ b2s,
                                          int s, int c)
{
    const float* hrow = &hs[s*JSTR];
    const float* wrow = &W2s[c*JSTR];
    float ax = 0.f, ay = 0.f, az = 0.f, aw = 0.f;
    #pragma unroll
    for (int j = 0; j < HIDn; j += 4) {
        float4 hv = *(const float4*)&hrow[j];
        float4 wv = *(const float4*)&wrow[j];
        ax = fmaf(hv.x, wv.x, ax); ay = fmaf(hv.y, wv.y, ay);
        az = fmaf(hv.z, wv.z, az); aw = fmaf(hv.w, wv.w, aw);
    }
    return (ax + ay) + (az + aw) + b2s[c];
}

__global__ void __launch_bounds__(NT, 3)
episode_kernel(const float* __restrict__ qg, const float* __restrict__ sg,
               const int*   __restrict__ tgg, const float* __restrict__ W1g,
               const float* __restrict__ b1g, const float* __restrict__ W2g,
               const float* __restrict__ b2g, float* __restrict__ out)
{
    extern __shared__ float sm[];
    float* W1T = sm + OFF_W1T;
    float* xs  = sm + OFF_XS;
    float* hs  = sm + OFF_HS;
    float* dhs = sm + OFF_DHS;
    float* W2s = sm + OFF_W2;
    float* ls  = sm + OFF_LS;
    float* dls = sm + OFF_DLS;
    float* b1s = sm + OFF_B1;
    float* b2s = sm + OFF_B2;
    int*   tgs = (int*)(sm + OFF_TG);

    const int e   = blockIdx.x;
    const int tid = threadIdx.x;
    const int tj  = tid & 31;
    const int r   = tid >> 5;

    // ---- load episode state into smem ----
    const float* W1e = W1g + (size_t)e * HIDn * FEATn;
    for (int idx = tid; idx < HIDn*FEATn; idx += NT) {
        int j = idx >> 6, k = idx & 63;          // global coalesced, smem transposed
        W1T[k*JSTR + j] = W1e[idx];
    }
    const float* W2e = W2g + (size_t)e * WAYn * HIDn;
    for (int idx = tid; idx < WAYn*HIDn; idx += NT) {
        int c = idx >> 7, j = idx & 127;
        W2s[c*JSTR + j] = W2e[idx];
    }
    const float* se = sg + (size_t)e * Sn * FEATn;
    for (int idx = tid; idx < Sn*FEATn; idx += NT) xs[idx] = se[idx];
    if (tid < HIDn) b1s[tid] = b1g[(size_t)e*HIDn + tid];
    if (tid < WAYn) b2s[tid] = b2g[(size_t)e*WAYn + tid];
    if (tid < Sn)   tgs[tid] = tgg[(size_t)e*Sn + tid];
    __syncthreads();

    // ---- 10 SGD steps on support set ----
    for (int it = 0; it < ITERSn; ++it) {
        // (1) fwd layer1
        fwd1(xs, W1T, b1s, hs, tj, r);
        __syncthreads();

        // (2) fwd layer2 -> logits
        if (tid < Sn*WAYn) {
            int s = tid / WAYn, c = tid % WAYn;
            ls[s*8 + c] = fwd2_one(hs, W2s, b2s, s, c);
        }
        __syncthreads();

        // (3) softmax grad: dlogits = (softmax - onehot)/S
        if (tid < Sn) {
            int s = tid;
            float m = ls[s*8];
            #pragma unroll
            for (int c = 1; c < WAYn; ++c) m = fmaxf(m, ls[s*8 + c]);
            float ex[WAYn]; float sum = 0.f;
            #pragma unroll
            for (int c = 0; c < WAYn; ++c) { ex[c] = expf(ls[s*8 + c] - m); sum += ex[c]; }
            float inv = 1.f / sum;
            int t = tgs[s];
            #pragma unroll
            for (int c = 0; c < WAYn; ++c)
                dls[s*8 + c] = (ex[c]*inv - (c == t ? 1.f : 0.f)) * (1.f / (float)Sn);
        }
        __syncthreads();

        // (4) dh = (dlogits @ W2) * relu'(h)   (uses pre-update W2)
        for (int idx = tid; idx < Sn*HIDn; idx += NT) {
            int s = idx >> 7, j = idx & 127;
            float hv = hs[s*JSTR + j];
            float d = 0.f;
            if (hv > 0.f) {
                #pragma unroll
                for (int c = 0; c < WAYn; ++c) d = fmaf(dls[s*8 + c], W2s[c*JSTR + j], d);
            }
            dhs[s*JSTR + j] = d;
        }
        __syncthreads();

        // (5) update W2, b2, b1
        for (int idx = tid; idx < WAYn*HIDn; idx += NT) {
            int c = idx >> 7, j = idx & 127;
            float g = 0.f;
            #pragma unroll 5
            for (int s = 0; s < Sn; ++s) g = fmaf(dls[s*8 + c], hs[s*JSTR + j], g);
            W2s[c*JSTR + j] -= LRc * g;
        }
        if (tid < HIDn) {
            float g = 0.f;
            #pragma unroll 5
            for (int s = 0; s < Sn; ++s) g += dhs[s*JSTR + tid];
            b1s[tid] -= LRc * g;
        }
        if (tid >= 128 && tid < 128 + WAYn) {
            int c = tid - 128;
            float g = 0.f;
            #pragma unroll 5
            for (int s = 0; s < Sn; ++s) g += dls[s*8 + c];
            b2s[c] -= LRc * g;
        }
        __syncthreads();

        // (6) fused dW1 + update on transposed layout:
        //     W1T[k][j] -= LR * sum_s dhs[s][j] * xs[s][k]
        // thread owns k in {r, r+8, ..., r+56} x j in [4tj, 4tj+4)
        {
            float4 acc[8];
            #pragma unroll
            for (int kk = 0; kk < 8; ++kk) acc[kk] = make_float4(0.f, 0.f, 0.f, 0.f);
            #pragma unroll 5
            for (int s = 0; s < Sn; ++s) {
                float4 dv = *(const float4*)&dhs[s*JSTR + 4*tj];
                const float* xrow = &xs[s*FEATn];
                #pragma unroll
                for (int kk = 0; kk < 8; ++kk) {
                    float xv = xrow[r + 8*kk];   // warp-uniform broadcast
                    acc[kk].x = fmaf(xv, dv.x, acc[kk].x);
                    acc[kk].y = fmaf(xv, dv.y, acc[kk].y);
                    acc[kk].z = fmaf(xv, dv.z, acc[kk].z);
                    acc[kk].w = fmaf(xv, dv.w, acc[kk].w);
                }
            }
            #pragma unroll
            for (int kk = 0; kk < 8; ++kk) {
                float4* p = (float4*)&W1T[(r + 8*kk)*JSTR + 4*tj];
                float4 w = *p;
                w.x -= LRc * acc[kk].x; w.y -= LRc * acc[kk].y;
                w.z -= LRc * acc[kk].z; w.w -= LRc * acc[kk].w;
                *p = w;
            }
        }
        __syncthreads();
    }

    // ---- query forward, 3 chunks of 25 rows ----
    for (int chunk = 0; chunk < 3; ++chunk) {
        const float* qe = qg + ((size_t)e * Qn + chunk * Sn) * FEATn;
        for (int idx = tid; idx < Sn*FEATn; idx += NT) xs[idx] = qe[idx];
        __syncthreads();

        fwd1(xs, W1T, b1s, hs, tj, r);
        __syncthreads();

        if (tid < Sn*WAYn) {
            int s = tid / WAYn, c = tid % WAYn;
            float v = fwd2_one(hs, W2s, b2s, s, c);
            out[((size_t)e * Qn + chunk * Sn + s) * WAYn + c] = v;
        }
        __syncthreads();
    }
}

extern "C" void kernel_launch(void* const* d_in, const int* in_sizes, int n_in,
                              void* d_out, int out_size) {
    const float* qf = (const float*)d_in[0];
    const float* sf = (const float*)d_in[1];
    const int*   st = (const int*)  d_in[2];
    const float* W1 = (const float*)d_in[3];
    const float* b1 = (const float*)d_in[4];
    const float* W2 = (const float*)d_in[5];
    const float* b2 = (const float*)d_in[6];
    float* out = (float*)d_out;

    size_t smem = (size_t)SMEMF * sizeof(float);
    cudaFuncSetAttribute(episode_kernel, cudaFuncAttributeMaxDynamicSharedMemorySize, (int)smem);
    episode_kernel<<<En, NT, smem>>>(qf, sf, st, W1, b1, W2, b2, out);
}